// round 4
// baseline (speedup 1.0000x reference)
#include <cuda_runtime.h>
#include <math.h>

#define IMG_W 4096
#define IMG_H 4096

#define BX 32
#define BY 8
#define TX 4
#define TY 16
#define GRID_X (IMG_W / (BX * TX))        // 32
#define GRID_Y (IMG_H / (BY * TY))        // 32
#define N_EDGE_BLOCKS (GRID_X * GRID_Y)   // 1024

#define KD_BLOCKS 64
#define TOTAL_BLOCKS (KD_BLOCKS + N_EDGE_BLOCKS)

__device__ float g_edge_partials[N_EDGE_BLOCKS];
__device__ float g_kd_partials[KD_BLOCKS];
__device__ unsigned int g_done_count;

__device__ __forceinline__ float fsqrt_approx(float x) {
    float r;
    asm("sqrt.approx.f32 %0, %1;" : "=f"(r) : "f"(x));
    return r;
}

__device__ __forceinline__ float warp_reduce_sum(float v) {
#pragma unroll
    for (int off = 16; off > 0; off >>= 1)
        v += __shfl_down_sync(0xFFFFFFFFu, v, off);
    return v;
}

// staged row load: aligned float4 only; halo via warp shuffle (+2 predicated
// scalar LDGs on the strip edges). Warp-uniform `row`.
struct Stage { float4 v; float l, r; };

__device__ __forceinline__ Stage load_stage(const float* __restrict__ img, int row,
                                            int x0, int lane) {
    Stage s;
    if ((unsigned)row >= (unsigned)IMG_H) {   // warp-uniform branch
        s.v = make_float4(0.f, 0.f, 0.f, 0.f);
        s.l = 0.f; s.r = 0.f;
        return s;
    }
    const float* p = img + (size_t)row * IMG_W;
    s.v = __ldg((const float4*)(p + x0));
    float lw = __shfl_up_sync(0xFFFFFFFFu, s.v.w, 1);
    float rw = __shfl_down_sync(0xFFFFFFFFu, s.v.x, 1);
    if (lane == 0)  lw = (x0 > 0) ? __ldg(p + x0 - 1) : 0.f;
    if (lane == 31) rw = (x0 + TX < IMG_W) ? __ldg(p + x0 + TX) : 0.f;
    s.l = lw; s.r = rw;
    return s;
}

__device__ __forceinline__ void expand(const Stage& s, float d[6]) {
    d[0] = s.l; d[1] = s.v.x; d[2] = s.v.y; d[3] = s.v.z; d[4] = s.v.w; d[5] = s.r;
}

// Sobel edge at (y,x) from zero-padded seg (kd path, scattered)
__device__ __forceinline__ float edge_at(const float* __restrict__ seg, int y, int x) {
    float v[3][3];
#pragma unroll
    for (int dy = 0; dy < 3; dy++)
#pragma unroll
        for (int dx = 0; dx < 3; dx++) {
            int yy = y - 1 + dy, xx = x - 1 + dx;
            v[dy][dx] = ((unsigned)yy < (unsigned)IMG_H && (unsigned)xx < (unsigned)IMG_W)
                        ? __ldg(seg + (size_t)yy * IMG_W + xx) : 0.0f;
        }
    float ex = (v[0][2] + 2.0f * v[1][2] + v[2][2]) - (v[0][0] + 2.0f * v[1][0] + v[2][0]);
    float ey = (v[2][0] + 2.0f * v[2][1] + v[2][2]) - (v[0][0] + 2.0f * v[0][1] + v[0][2]);
    return fsqrt_approx(ex * ex + ey * ey);
}

// ---------------------------------------------------------------------------
__global__ __launch_bounds__(256, 4)
void fused_kernel(const float* __restrict__ pred, const float* __restrict__ tgt,
                  const float* __restrict__ kp, int K, float* __restrict__ out) {
    const int tid = threadIdx.x;
    const int lane = tid & 31;
    const int wid  = tid >> 5;
    float acc = 0.0f;
    __shared__ float sred[8];
    __shared__ bool s_last;

    if (blockIdx.x < KD_BLOCKS) {
        // ---- keypoint path: kd(k) = sum_{du,dv in -1..2} Wx*Wy*edge ----
        const int idx = blockIdx.x * 256 + tid;
        const int k    = idx >> 4;
        const int cell = idx & 15;
        if (k < K) {
            float gx = __ldg(kp + 2 * k);
            float gy = __ldg(kp + 2 * k + 1);
            float fx = (gx + 1.0f) * (IMG_W * 0.5f) - 0.5f;
            float fy = (gy + 1.0f) * (IMG_H * 0.5f) - 0.5f;
            float flx = floorf(fx), fly = floorf(fy);
            int x0 = (int)flx, y0 = (int)fly;
            float wx1 = fx - flx, wy1 = fy - fly;
            float wx0 = 1.0f - wx1, wy0 = 1.0f - wy1;
            float ax0 = ((unsigned)x0 < (unsigned)IMG_W) ? wx0 : 0.0f;
            float ax1 = ((unsigned)(x0 + 1) < (unsigned)IMG_W) ? wx1 : 0.0f;
            float ay0 = ((unsigned)y0 < (unsigned)IMG_H) ? wy0 : 0.0f;
            float ay1 = ((unsigned)(y0 + 1) < (unsigned)IMG_H) ? wy1 : 0.0f;

            int du = (cell & 3) - 1;
            int dv = (cell >> 2) - 1;
            float Wx = ((du <= 1) ? ax0 : 0.0f) + ((du >= 0) ? ax1 : 0.0f);
            float Wy = ((dv <= 1) ? ay0 : 0.0f) + ((dv >= 0) ? ay1 : 0.0f);
            float W = Wx * Wy;
            int cx = x0 + du, cy = y0 + dv;
            if (W != 0.0f && (unsigned)cx < (unsigned)IMG_W && (unsigned)cy < (unsigned)IMG_H)
                acc = W * edge_at(pred, cy, cx);
        }
        float ws = warp_reduce_sum(acc);
        if (lane == 0) sred[wid] = ws;
        __syncthreads();
        if (wid == 0) {
            float v = (lane < 8) ? sred[lane] : 0.0f;
            v = warp_reduce_sum(v);
            if (lane == 0) g_kd_partials[blockIdx.x] = v;
        }
    } else {
        // ---- edge-loss path: float4 loads + shuffle halo + 1-deep pipeline ----
        const int bid = blockIdx.x - KD_BLOCKS;
        const int bx = bid % GRID_X;
        const int by = bid / GRID_X;
        const int x0 = (bx * BX + lane) * TX;
        const int y0 = (by * BY + wid) * TY;

        float P[3][6], T[3][6];
        expand(load_stage(pred, y0 - 1, x0, lane), P[0]);
        expand(load_stage(tgt,  y0 - 1, x0, lane), T[0]);
        expand(load_stage(pred, y0,     x0, lane), P[1]);
        expand(load_stage(tgt,  y0,     x0, lane), T[1]);

        Stage sp = load_stage(pred, y0 + 1, x0, lane);
        Stage st = load_stage(tgt,  y0 + 1, x0, lane);

#pragma unroll
        for (int t = 0; t < TY; t++) {
            const int am = t % 3, bm = (t + 1) % 3, cm = (t + 2) % 3;
            // row t+1 arrives from staged loads issued last iteration
            expand(sp, P[cm]);
            expand(st, T[cm]);
            // issue loads for row t+2 (consumed next iteration)
            if (t + 1 < TY) {
                sp = load_stage(pred, y0 + t + 2, x0, lane);
                st = load_stage(tgt,  y0 + t + 2, x0, lane);
            }

            const float* pa = P[am]; const float* pb = P[bm]; const float* pc = P[cm];
            const float* ta = T[am]; const float* tb = T[bm]; const float* tc = T[cm];
#pragma unroll
            for (int j = 0; j < TX; j++) {
                float pex = (pa[j + 2] + 2.0f * pb[j + 2] + pc[j + 2])
                          - (pa[j]     + 2.0f * pb[j]     + pc[j]);
                float pey = (pc[j] - pa[j]) + 2.0f * (pc[j + 1] - pa[j + 1]) + (pc[j + 2] - pa[j + 2]);
                float pe  = fsqrt_approx(pex * pex + pey * pey);
                float tex = (ta[j + 2] + 2.0f * tb[j + 2] + tc[j + 2])
                          - (ta[j]     + 2.0f * tb[j]     + tc[j]);
                float tey = (tc[j] - ta[j]) + 2.0f * (tc[j + 1] - ta[j + 1]) + (tc[j + 2] - ta[j + 2]);
                float te  = fsqrt_approx(tex * tex + tey * tey);
                float df  = pe - te;
                acc += df * df;
            }
        }

        float ws = warp_reduce_sum(acc);
        if (lane == 0) sred[wid] = ws;
        __syncthreads();
        if (wid == 0) {
            float v = (lane < 8) ? sred[lane] : 0.0f;
            v = warp_reduce_sum(v);
            if (lane == 0) g_edge_partials[bid] = v;
        }
    }

    // ---- grid-wide completion; last block reduces everything ----
    __threadfence();
    if (tid == 0) {
        unsigned int prev = atomicAdd(&g_done_count, 1u);
        s_last = (prev == TOTAL_BLOCKS - 1);
    }
    __syncthreads();
    if (!s_last) return;

    float e = 0.0f, kv = 0.0f;
    for (int i = tid; i < N_EDGE_BLOCKS; i += 256) e += g_edge_partials[i];
    if (tid < KD_BLOCKS) kv = g_kd_partials[tid];

    __shared__ float se[8], sk[8];
    float we = warp_reduce_sum(e);
    float wk = warp_reduce_sum(kv);
    if (lane == 0) { se[wid] = we; sk[wid] = wk; }
    __syncthreads();
    if (wid == 0) {
        float ve = (lane < 8) ? se[lane] : 0.0f;
        float vk = (lane < 8) ? sk[lane] : 0.0f;
        ve = warp_reduce_sum(ve);
        vk = warp_reduce_sum(vk);
        if (lane == 0) {
            float edge_loss = ve * (1.0f / ((float)IMG_W * (float)IMG_H));
            float constraint = vk / (float)K;
            out[0] = 1.0f * edge_loss + 0.5f * constraint;
            g_done_count = 0;
        }
    }
}

// ---------------------------------------------------------------------------
extern "C" void kernel_launch(void* const* d_in, const int* in_sizes, int n_in,
                              void* d_out, int out_size) {
    const float* kp   = (const float*)d_in[0];
    const float* pred = (const float*)d_in[2];
    const float* tgt  = (const float*)d_in[3];
    const int K = in_sizes[0] / 2;

    fused_kernel<<<TOTAL_BLOCKS, 256>>>(pred, tgt, kp, K, (float*)d_out);
}

// round 5
// speedup vs baseline: 1.4751x; 1.4751x over previous
#include <cuda_runtime.h>
#include <math.h>

#define IMG_W 4096
#define IMG_H 4096

#define BX 32
#define BY 8
#define TX 4
#define TY 16
#define GRID_X (IMG_W / (BX * TX))        // 32
#define GRID_Y (IMG_H / (BY * TY))        // 32
#define N_EDGE_BLOCKS (GRID_X * GRID_Y)   // 1024

#define KD_BLOCKS 64
#define TOTAL_BLOCKS (KD_BLOCKS + N_EDGE_BLOCKS)

__device__ float g_edge_partials[N_EDGE_BLOCKS];
__device__ float g_kd_partials[KD_BLOCKS];
__device__ unsigned int g_done_count;

__device__ __forceinline__ float fsqrt_approx(float x) {
    float r;
    asm("sqrt.approx.f32 %0, %1;" : "=f"(r) : "f"(x));
    return r;
}

__device__ __forceinline__ float warp_reduce_sum(float v) {
#pragma unroll
    for (int off = 16; off > 0; off >>= 1)
        v += __shfl_down_sync(0xFFFFFFFFu, v, off);
    return v;
}

// direct row load: s[0..5] = img[row][x0-1 .. x0+4]; zero outside image.
// 3 LDGs (scalar, float4, scalar) — no shuffles, so a staged load has no
// consume-at-issue dependency and can stay in flight a full iteration.
struct Stage { float s[6]; };

__device__ __forceinline__ Stage load_row(const float* __restrict__ img, int row,
                                          int x0, bool xedge) {
    Stage st;
    if ((unsigned)row >= (unsigned)IMG_H) {
#pragma unroll
        for (int i = 0; i < 6; i++) st.s[i] = 0.0f;
        return st;
    }
    const float* p = img + (size_t)row * IMG_W;
    if (!xedge) {
        float4 v = __ldg((const float4*)(p + x0));
        st.s[0] = __ldg(p + x0 - 1);
        st.s[1] = v.x; st.s[2] = v.y; st.s[3] = v.z; st.s[4] = v.w;
        st.s[5] = __ldg(p + x0 + 4);
    } else {
#pragma unroll
        for (int i = 0; i < 6; i++) {
            int xx = x0 - 1 + i;
            st.s[i] = ((unsigned)xx < (unsigned)IMG_W) ? __ldg(p + xx) : 0.0f;
        }
    }
    return st;
}

// Sobel edge at (y,x) from zero-padded seg (kd path, scattered)
__device__ __forceinline__ float edge_at(const float* __restrict__ seg, int y, int x) {
    float v[3][3];
#pragma unroll
    for (int dy = 0; dy < 3; dy++)
#pragma unroll
        for (int dx = 0; dx < 3; dx++) {
            int yy = y - 1 + dy, xx = x - 1 + dx;
            v[dy][dx] = ((unsigned)yy < (unsigned)IMG_H && (unsigned)xx < (unsigned)IMG_W)
                        ? __ldg(seg + (size_t)yy * IMG_W + xx) : 0.0f;
        }
    float ex = (v[0][2] + 2.0f * v[1][2] + v[2][2]) - (v[0][0] + 2.0f * v[1][0] + v[2][0]);
    float ey = (v[2][0] + 2.0f * v[2][1] + v[2][2]) - (v[0][0] + 2.0f * v[0][1] + v[0][2]);
    return fsqrt_approx(ex * ex + ey * ey);
}

// ---------------------------------------------------------------------------
__global__ __launch_bounds__(256, 3)
void fused_kernel(const float* __restrict__ pred, const float* __restrict__ tgt,
                  const float* __restrict__ kp, int K, float* __restrict__ out) {
    const int tid = threadIdx.x;
    const int lane = tid & 31;
    const int wid  = tid >> 5;
    float acc = 0.0f;
    __shared__ float sred[8];
    __shared__ bool s_last;

    if (blockIdx.x < KD_BLOCKS) {
        // ---- keypoint path: kd(k) = sum_{du,dv in -1..2} Wx*Wy*edge ----
        const int idx = blockIdx.x * 256 + tid;
        const int k    = idx >> 4;
        const int cell = idx & 15;
        if (k < K) {
            float gx = __ldg(kp + 2 * k);
            float gy = __ldg(kp + 2 * k + 1);
            float fx = (gx + 1.0f) * (IMG_W * 0.5f) - 0.5f;
            float fy = (gy + 1.0f) * (IMG_H * 0.5f) - 0.5f;
            float flx = floorf(fx), fly = floorf(fy);
            int x0 = (int)flx, y0 = (int)fly;
            float wx1 = fx - flx, wy1 = fy - fly;
            float wx0 = 1.0f - wx1, wy0 = 1.0f - wy1;
            float ax0 = ((unsigned)x0 < (unsigned)IMG_W) ? wx0 : 0.0f;
            float ax1 = ((unsigned)(x0 + 1) < (unsigned)IMG_W) ? wx1 : 0.0f;
            float ay0 = ((unsigned)y0 < (unsigned)IMG_H) ? wy0 : 0.0f;
            float ay1 = ((unsigned)(y0 + 1) < (unsigned)IMG_H) ? wy1 : 0.0f;

            int du = (cell & 3) - 1;
            int dv = (cell >> 2) - 1;
            float Wx = ((du <= 1) ? ax0 : 0.0f) + ((du >= 0) ? ax1 : 0.0f);
            float Wy = ((dv <= 1) ? ay0 : 0.0f) + ((dv >= 0) ? ay1 : 0.0f);
            float W = Wx * Wy;
            int cx = x0 + du, cy = y0 + dv;
            if (W != 0.0f && (unsigned)cx < (unsigned)IMG_W && (unsigned)cy < (unsigned)IMG_H)
                acc = W * edge_at(pred, cy, cx);
        }
        float ws = warp_reduce_sum(acc);
        if (lane == 0) sred[wid] = ws;
        __syncthreads();
        if (wid == 0) {
            float v = (lane < 8) ? sred[lane] : 0.0f;
            v = warp_reduce_sum(v);
            if (lane == 0) g_kd_partials[blockIdx.x] = v;
        }
    } else {
        // ---- edge-loss path: direct loads, staged one iteration ahead ----
        const int bid = blockIdx.x - KD_BLOCKS;
        const int bx = bid % GRID_X;
        const int by = bid / GRID_X;
        const int x0 = (bx * BX + lane) * TX;
        const int y0 = (by * BY + wid) * TY;
        const bool xedge = (x0 == 0) || (x0 + TX >= IMG_W);

        float P[3][6], T[3][6];
        {
            Stage a = load_row(pred, y0 - 1, x0, xedge);
            Stage b = load_row(tgt,  y0 - 1, x0, xedge);
            Stage c = load_row(pred, y0,     x0, xedge);
            Stage d = load_row(tgt,  y0,     x0, xedge);
#pragma unroll
            for (int i = 0; i < 6; i++) { P[0][i] = a.s[i]; T[0][i] = b.s[i];
                                          P[1][i] = c.s[i]; T[1][i] = d.s[i]; }
        }
        Stage sp = load_row(pred, y0 + 1, x0, xedge);
        Stage st = load_row(tgt,  y0 + 1, x0, xedge);

#pragma unroll
        for (int t = 0; t < TY; t++) {
            const int am = t % 3, bm = (t + 1) % 3, cm = (t + 2) % 3;
            // row t+1 (staged last iteration) lands in the ring
#pragma unroll
            for (int i = 0; i < 6; i++) { P[cm][i] = sp.s[i]; T[cm][i] = st.s[i]; }
            // stage row t+2 now; consumed next iteration
            if (t + 1 < TY) {
                sp = load_row(pred, y0 + t + 2, x0, xedge);
                st = load_row(tgt,  y0 + t + 2, x0, xedge);
            }

            const float* pa = P[am]; const float* pb = P[bm]; const float* pc = P[cm];
            const float* ta = T[am]; const float* tb = T[bm]; const float* tc = T[cm];
#pragma unroll
            for (int j = 0; j < TX; j++) {
                float pex = (pa[j + 2] + 2.0f * pb[j + 2] + pc[j + 2])
                          - (pa[j]     + 2.0f * pb[j]     + pc[j]);
                float pey = (pc[j] - pa[j]) + 2.0f * (pc[j + 1] - pa[j + 1]) + (pc[j + 2] - pa[j + 2]);
                float pe  = fsqrt_approx(pex * pex + pey * pey);
                float tex = (ta[j + 2] + 2.0f * tb[j + 2] + tc[j + 2])
                          - (ta[j]     + 2.0f * tb[j]     + tc[j]);
                float tey = (tc[j] - ta[j]) + 2.0f * (tc[j + 1] - ta[j + 1]) + (tc[j + 2] - ta[j + 2]);
                float te  = fsqrt_approx(tex * tex + tey * tey);
                float df  = pe - te;
                acc += df * df;
            }
        }

        float ws = warp_reduce_sum(acc);
        if (lane == 0) sred[wid] = ws;
        __syncthreads();
        if (wid == 0) {
            float v = (lane < 8) ? sred[lane] : 0.0f;
            v = warp_reduce_sum(v);
            if (lane == 0) g_edge_partials[bid] = v;
        }
    }

    // ---- grid-wide completion; last block reduces everything ----
    __threadfence();
    if (tid == 0) {
        unsigned int prev = atomicAdd(&g_done_count, 1u);
        s_last = (prev == TOTAL_BLOCKS - 1);
    }
    __syncthreads();
    if (!s_last) return;

    float e = 0.0f, kv = 0.0f;
    for (int i = tid; i < N_EDGE_BLOCKS; i += 256) e += g_edge_partials[i];
    if (tid < KD_BLOCKS) kv = g_kd_partials[tid];

    __shared__ float se[8], sk[8];
    float we = warp_reduce_sum(e);
    float wk = warp_reduce_sum(kv);
    if (lane == 0) { se[wid] = we; sk[wid] = wk; }
    __syncthreads();
    if (wid == 0) {
        float ve = (lane < 8) ? se[lane] : 0.0f;
        float vk = (lane < 8) ? sk[lane] : 0.0f;
        ve = warp_reduce_sum(ve);
        vk = warp_reduce_sum(vk);
        if (lane == 0) {
            float edge_loss = ve * (1.0f / ((float)IMG_W * (float)IMG_H));
            float constraint = vk / (float)K;
            out[0] = 1.0f * edge_loss + 0.5f * constraint;
            g_done_count = 0;
        }
    }
}

// ---------------------------------------------------------------------------
extern "C" void kernel_launch(void* const* d_in, const int* in_sizes, int n_in,
                              void* d_out, int out_size) {
    const float* kp   = (const float*)d_in[0];
    const float* pred = (const float*)d_in[2];
    const float* tgt  = (const float*)d_in[3];
    const int K = in_sizes[0] / 2;

    fused_kernel<<<TOTAL_BLOCKS, 256>>>(pred, tgt, kp, K, (float*)d_out);
}

// round 6
// speedup vs baseline: 1.5452x; 1.0475x over previous
#include <cuda_runtime.h>
#include <math.h>

#define IMG_W 4096
#define IMG_H 4096

#define BX 32
#define BY 8
#define TX 4
#define TY 16
#define GRID_X (IMG_W / (BX * TX))        // 32
#define GRID_Y (IMG_H / (BY * TY))        // 32
#define N_EDGE_BLOCKS (GRID_X * GRID_Y)   // 1024

#define KD_BLOCKS 64
#define TOTAL_BLOCKS (KD_BLOCKS + N_EDGE_BLOCKS)

__device__ float g_edge_partials[N_EDGE_BLOCKS];
__device__ float g_kd_partials[KD_BLOCKS];
__device__ unsigned int g_done_count;

typedef unsigned long long u64;

// ---- packed f32x2 helpers (Blackwell FFMA2 path) ----
__device__ __forceinline__ u64 pack2(float lo, float hi) {
    u64 r; asm("mov.b64 %0, {%1, %2};" : "=l"(r) : "f"(lo), "f"(hi)); return r;
}
__device__ __forceinline__ void unpack2(u64 v, float& lo, float& hi) {
    asm("mov.b64 {%0, %1}, %2;" : "=f"(lo), "=f"(hi) : "l"(v));
}
__device__ __forceinline__ u64 add2(u64 a, u64 b) {
    u64 r; asm("add.rn.f32x2 %0, %1, %2;" : "=l"(r) : "l"(a), "l"(b)); return r;
}
__device__ __forceinline__ u64 mul2(u64 a, u64 b) {
    u64 r; asm("mul.rn.f32x2 %0, %1, %2;" : "=l"(r) : "l"(a), "l"(b)); return r;
}
__device__ __forceinline__ u64 fma2(u64 a, u64 b, u64 c) {
    u64 r; asm("fma.rn.f32x2 %0, %1, %2, %3;" : "=l"(r) : "l"(a), "l"(b), "l"(c)); return r;
}

__device__ __forceinline__ float fsqrt_approx(float x) {
    float r;
    asm("sqrt.approx.f32 %0, %1;" : "=f"(r) : "f"(x));
    return r;
}

__device__ __forceinline__ float warp_reduce_sum(float v) {
#pragma unroll
    for (int off = 16; off > 0; off >>= 1)
        v += __shfl_down_sync(0xFFFFFFFFu, v, off);
    return v;
}

// direct row load: s[0..5] = img[row][x0-1 .. x0+4]; zero outside image.
struct Stage { float s[6]; };

__device__ __forceinline__ Stage load_row(const float* __restrict__ img, int row,
                                          int x0, bool xedge) {
    Stage st;
    if ((unsigned)row >= (unsigned)IMG_H) {
#pragma unroll
        for (int i = 0; i < 6; i++) st.s[i] = 0.0f;
        return st;
    }
    const float* p = img + (size_t)row * IMG_W;
    if (!xedge) {
        float4 v = __ldg((const float4*)(p + x0));
        st.s[0] = __ldg(p + x0 - 1);
        st.s[1] = v.x; st.s[2] = v.y; st.s[3] = v.z; st.s[4] = v.w;
        st.s[5] = __ldg(p + x0 + 4);
    } else {
#pragma unroll
        for (int i = 0; i < 6; i++) {
            int xx = x0 - 1 + i;
            st.s[i] = ((unsigned)xx < (unsigned)IMG_W) ? __ldg(p + xx) : 0.0f;
        }
    }
    return st;
}

// Sobel edge at (y,x) from zero-padded seg (kd path, scattered)
__device__ __forceinline__ float edge_at(const float* __restrict__ seg, int y, int x) {
    float v[3][3];
#pragma unroll
    for (int dy = 0; dy < 3; dy++)
#pragma unroll
        for (int dx = 0; dx < 3; dx++) {
            int yy = y - 1 + dy, xx = x - 1 + dx;
            v[dy][dx] = ((unsigned)yy < (unsigned)IMG_H && (unsigned)xx < (unsigned)IMG_W)
                        ? __ldg(seg + (size_t)yy * IMG_W + xx) : 0.0f;
        }
    float ex = (v[0][2] + 2.0f * v[1][2] + v[2][2]) - (v[0][0] + 2.0f * v[1][0] + v[2][0]);
    float ey = (v[2][0] + 2.0f * v[2][1] + v[2][2]) - (v[0][0] + 2.0f * v[0][1] + v[0][2]);
    return fsqrt_approx(ex * ex + ey * ey);
}

// ---------------------------------------------------------------------------
__global__ __launch_bounds__(256, 3)
void fused_kernel(const float* __restrict__ pred, const float* __restrict__ tgt,
                  const float* __restrict__ kp, int K, float* __restrict__ out) {
    const int tid = threadIdx.x;
    const int lane = tid & 31;
    const int wid  = tid >> 5;
    float acc = 0.0f;
    __shared__ float sred[8];
    __shared__ bool s_last;

    if (blockIdx.x < KD_BLOCKS) {
        // ---- keypoint path: kd(k) = sum_{du,dv in -1..2} Wx*Wy*edge ----
        const int idx = blockIdx.x * 256 + tid;
        const int k    = idx >> 4;
        const int cell = idx & 15;
        if (k < K) {
            float gx = __ldg(kp + 2 * k);
            float gy = __ldg(kp + 2 * k + 1);
            float fx = (gx + 1.0f) * (IMG_W * 0.5f) - 0.5f;
            float fy = (gy + 1.0f) * (IMG_H * 0.5f) - 0.5f;
            float flx = floorf(fx), fly = floorf(fy);
            int x0 = (int)flx, y0 = (int)fly;
            float wx1 = fx - flx, wy1 = fy - fly;
            float wx0 = 1.0f - wx1, wy0 = 1.0f - wy1;
            float ax0 = ((unsigned)x0 < (unsigned)IMG_W) ? wx0 : 0.0f;
            float ax1 = ((unsigned)(x0 + 1) < (unsigned)IMG_W) ? wx1 : 0.0f;
            float ay0 = ((unsigned)y0 < (unsigned)IMG_H) ? wy0 : 0.0f;
            float ay1 = ((unsigned)(y0 + 1) < (unsigned)IMG_H) ? wy1 : 0.0f;

            int du = (cell & 3) - 1;
            int dv = (cell >> 2) - 1;
            float Wx = ((du <= 1) ? ax0 : 0.0f) + ((du >= 0) ? ax1 : 0.0f);
            float Wy = ((dv <= 1) ? ay0 : 0.0f) + ((dv >= 0) ? ay1 : 0.0f);
            float W = Wx * Wy;
            int cx = x0 + du, cy = y0 + dv;
            if (W != 0.0f && (unsigned)cx < (unsigned)IMG_W && (unsigned)cy < (unsigned)IMG_H)
                acc = W * edge_at(pred, cy, cx);
        }
        float ws = warp_reduce_sum(acc);
        if (lane == 0) sred[wid] = ws;
        __syncthreads();
        if (wid == 0) {
            float v = (lane < 8) ? sred[lane] : 0.0f;
            v = warp_reduce_sum(v);
            if (lane == 0) g_kd_partials[blockIdx.x] = v;
        }
    } else {
        // ---- edge-loss path: staged loads + packed f32x2 stencil ----
        const int bid = blockIdx.x - KD_BLOCKS;
        const int bx = bid % GRID_X;
        const int by = bid / GRID_X;
        const int x0 = (bx * BX + lane) * TX;
        const int y0 = (by * BY + wid) * TY;
        const bool xedge = (x0 == 0) || (x0 + TX >= IMG_W);

        const u64 TWO2  = pack2(2.0f, 2.0f);
        const u64 NEG12 = pack2(-1.0f, -1.0f);

        // ring of packed (pred, tgt) rows
        u64 PT[3][6];
        {
            Stage a = load_row(pred, y0 - 1, x0, xedge);
            Stage b = load_row(tgt,  y0 - 1, x0, xedge);
            Stage c = load_row(pred, y0,     x0, xedge);
            Stage d = load_row(tgt,  y0,     x0, xedge);
#pragma unroll
            for (int i = 0; i < 6; i++) {
                PT[0][i] = pack2(a.s[i], b.s[i]);
                PT[1][i] = pack2(c.s[i], d.s[i]);
            }
        }
        Stage sp = load_row(pred, y0 + 1, x0, xedge);
        Stage st = load_row(tgt,  y0 + 1, x0, xedge);

#pragma unroll
        for (int t = 0; t < TY; t++) {
            const int am = t % 3, bm = (t + 1) % 3, cm = (t + 2) % 3;
            // consume staged row t+1
#pragma unroll
            for (int i = 0; i < 6; i++) PT[cm][i] = pack2(sp.s[i], st.s[i]);
            // stage row t+2
            if (t + 1 < TY) {
                sp = load_row(pred, y0 + t + 2, x0, xedge);
                st = load_row(tgt,  y0 + t + 2, x0, xedge);
            }

            const u64* ra = PT[am]; const u64* rb = PT[bm]; const u64* rc = PT[cm];
            u64 cs[6], dd[6];
#pragma unroll
            for (int i = 0; i < 6; i++) {
                cs[i] = add2(fma2(rb[i], TWO2, ra[i]), rc[i]);   // a + 2b + c
                dd[i] = fma2(ra[i], NEG12, rc[i]);               // c - a
            }
#pragma unroll
            for (int j = 0; j < 4; j++) {
                u64 ex = fma2(cs[j], NEG12, cs[j + 2]);          // cs[j+2] - cs[j]
                u64 ey = add2(fma2(dd[j + 1], TWO2, dd[j]), dd[j + 2]);
                u64 s2 = fma2(ey, ey, mul2(ex, ex));
                float p2, t2;
                unpack2(s2, p2, t2);
                float df = fsqrt_approx(p2) - fsqrt_approx(t2);
                acc = fmaf(df, df, acc);
            }
        }

        float ws = warp_reduce_sum(acc);
        if (lane == 0) sred[wid] = ws;
        __syncthreads();
        if (wid == 0) {
            float v = (lane < 8) ? sred[lane] : 0.0f;
            v = warp_reduce_sum(v);
            if (lane == 0) g_edge_partials[bid] = v;
        }
    }

    // ---- grid-wide completion; last block reduces everything ----
    __threadfence();
    if (tid == 0) {
        unsigned int prev = atomicAdd(&g_done_count, 1u);
        s_last = (prev == TOTAL_BLOCKS - 1);
    }
    __syncthreads();
    if (!s_last) return;

    float e = 0.0f, kv = 0.0f;
    for (int i = tid; i < N_EDGE_BLOCKS; i += 256) e += g_edge_partials[i];
    if (tid < KD_BLOCKS) kv = g_kd_partials[tid];

    __shared__ float se[8], sk[8];
    float we = warp_reduce_sum(e);
    float wk = warp_reduce_sum(kv);
    if (lane == 0) { se[wid] = we; sk[wid] = wk; }
    __syncthreads();
    if (wid == 0) {
        float ve = (lane < 8) ? se[lane] : 0.0f;
        float vk = (lane < 8) ? sk[lane] : 0.0f;
        ve = warp_reduce_sum(ve);
        vk = warp_reduce_sum(vk);
        if (lane == 0) {
            float edge_loss = ve * (1.0f / ((float)IMG_W * (float)IMG_H));
            float constraint = vk / (float)K;
            out[0] = 1.0f * edge_loss + 0.5f * constraint;
            g_done_count = 0;
        }
    }
}

// ---------------------------------------------------------------------------
extern "C" void kernel_launch(void* const* d_in, const int* in_sizes, int n_in,
                              void* d_out, int out_size) {
    const float* kp   = (const float*)d_in[0];
    const float* pred = (const float*)d_in[2];
    const float* tgt  = (const float*)d_in[3];
    const int K = in_sizes[0] / 2;

    fused_kernel<<<TOTAL_BLOCKS, 256>>>(pred, tgt, kp, K, (float*)d_out);
}

// round 8
// speedup vs baseline: 1.6871x; 1.0918x over previous
#include <cuda_runtime.h>
#include <math.h>
#include <stdint.h>

#define IMG_W 4096
#define IMG_H 4096

#define BX 32
#define BY 8
#define TX 4
#define TY 16
#define GRID_X (IMG_W / (BX * TX))        // 32
#define GRID_Y (IMG_H / (BY * TY))        // 32
#define N_EDGE_BLOCKS (GRID_X * GRID_Y)   // 1024

#define KD_BLOCKS 64
#define TOTAL_BLOCKS (KD_BLOCKS + N_EDGE_BLOCKS)

#define DEPTH 5            // smem ring depth (rows in flight per warp)
#define ROWF 132           // floats per staged row: [0..127]=px, 128=L, 129=R, 2 pad

__device__ float g_edge_partials[N_EDGE_BLOCKS];
__device__ float g_kd_partials[KD_BLOCKS];
__device__ unsigned int g_done_count;

typedef unsigned long long u64;

// ---- packed f32x2 helpers ----
__device__ __forceinline__ u64 pack2(float lo, float hi) {
    u64 r; asm("mov.b64 %0, {%1, %2};" : "=l"(r) : "f"(lo), "f"(hi)); return r;
}
__device__ __forceinline__ void unpack2(u64 v, float& lo, float& hi) {
    asm("mov.b64 {%0, %1}, %2;" : "=f"(lo), "=f"(hi) : "l"(v));
}
__device__ __forceinline__ u64 add2(u64 a, u64 b) {
    u64 r; asm("add.rn.f32x2 %0, %1, %2;" : "=l"(r) : "l"(a), "l"(b)); return r;
}
__device__ __forceinline__ u64 mul2(u64 a, u64 b) {
    u64 r; asm("mul.rn.f32x2 %0, %1, %2;" : "=l"(r) : "l"(a), "l"(b)); return r;
}
__device__ __forceinline__ u64 fma2(u64 a, u64 b, u64 c) {
    u64 r; asm("fma.rn.f32x2 %0, %1, %2, %3;" : "=l"(r) : "l"(a), "l"(b), "l"(c)); return r;
}

__device__ __forceinline__ float fsqrt_approx(float x) {
    float r; asm("sqrt.approx.f32 %0, %1;" : "=f"(r) : "f"(x)); return r;
}

__device__ __forceinline__ float warp_reduce_sum(float v) {
#pragma unroll
    for (int off = 16; off > 0; off >>= 1)
        v += __shfl_down_sync(0xFFFFFFFFu, v, off);
    return v;
}

// ---- cp.async primitives ----
__device__ __forceinline__ void cp16(uint32_t dst, const float* src) {
    asm volatile("cp.async.cg.shared.global [%0], [%1], 16;" :: "r"(dst), "l"(src));
}
__device__ __forceinline__ void cp4(uint32_t dst, const float* src) {
    asm volatile("cp.async.ca.shared.global [%0], [%1], 4;" :: "r"(dst), "l"(src));
}
__device__ __forceinline__ void cp_commit() {
    asm volatile("cp.async.commit_group;" ::: "memory");
}
__device__ __forceinline__ void cp_wait_3() {
    asm volatile("cp.async.wait_group 3;" ::: "memory");   // DEPTH-2
}

// Sobel edge at (y,x) from zero-padded seg (kd path, scattered)
__device__ __forceinline__ float edge_at(const float* __restrict__ seg, int y, int x) {
    float v[3][3];
#pragma unroll
    for (int dy = 0; dy < 3; dy++)
#pragma unroll
        for (int dx = 0; dx < 3; dx++) {
            int yy = y - 1 + dy, xx = x - 1 + dx;
            v[dy][dx] = ((unsigned)yy < (unsigned)IMG_H && (unsigned)xx < (unsigned)IMG_W)
                        ? __ldg(seg + (size_t)yy * IMG_W + xx) : 0.0f;
        }
    float ex = (v[0][2] + 2.0f * v[1][2] + v[2][2]) - (v[0][0] + 2.0f * v[1][0] + v[2][0]);
    float ey = (v[2][0] + 2.0f * v[2][1] + v[2][2]) - (v[0][0] + 2.0f * v[0][1] + v[0][2]);
    return fsqrt_approx(ex * ex + ey * ey);
}

// ---------------------------------------------------------------------------
__global__ __launch_bounds__(256, 3)
void fused_kernel(const float* __restrict__ pred, const float* __restrict__ tgt,
                  const float* __restrict__ kp, int K, float* __restrict__ out) {
    const int tid = threadIdx.x;
    const int lane = tid & 31;
    const int wid  = tid >> 5;
    float acc = 0.0f;
    __shared__ float sred[8];
    __shared__ bool s_last;
    // per-warp staging rings: [warp][slot][img][ROWF]; 16B-aligned for
    // cp.async.16 destinations and float4 consume loads
    __shared__ __align__(16) float s_ring[8 * DEPTH * 2 * ROWF];

    if (blockIdx.x < KD_BLOCKS) {
        // ---- keypoint path: kd(k) = sum_{du,dv in -1..2} Wx*Wy*edge ----
        const int idx = blockIdx.x * 256 + tid;
        const int k    = idx >> 4;
        const int cell = idx & 15;
        if (k < K) {
            float gx = __ldg(kp + 2 * k);
            float gy = __ldg(kp + 2 * k + 1);
            float fx = (gx + 1.0f) * (IMG_W * 0.5f) - 0.5f;
            float fy = (gy + 1.0f) * (IMG_H * 0.5f) - 0.5f;
            float flx = floorf(fx), fly = floorf(fy);
            int x0 = (int)flx, y0 = (int)fly;
            float wx1 = fx - flx, wy1 = fy - fly;
            float wx0 = 1.0f - wx1, wy0 = 1.0f - wy1;
            float ax0 = ((unsigned)x0 < (unsigned)IMG_W) ? wx0 : 0.0f;
            float ax1 = ((unsigned)(x0 + 1) < (unsigned)IMG_W) ? wx1 : 0.0f;
            float ay0 = ((unsigned)y0 < (unsigned)IMG_H) ? wy0 : 0.0f;
            float ay1 = ((unsigned)(y0 + 1) < (unsigned)IMG_H) ? wy1 : 0.0f;

            int du = (cell & 3) - 1;
            int dv = (cell >> 2) - 1;
            float Wx = ((du <= 1) ? ax0 : 0.0f) + ((du >= 0) ? ax1 : 0.0f);
            float Wy = ((dv <= 1) ? ay0 : 0.0f) + ((dv >= 0) ? ay1 : 0.0f);
            float W = Wx * Wy;
            int cx = x0 + du, cy = y0 + dv;
            if (W != 0.0f && (unsigned)cx < (unsigned)IMG_W && (unsigned)cy < (unsigned)IMG_H)
                acc = W * edge_at(pred, cy, cx);
        }
        float ws = warp_reduce_sum(acc);
        if (lane == 0) sred[wid] = ws;
        __syncthreads();
        if (wid == 0) {
            float v = (lane < 8) ? sred[lane] : 0.0f;
            v = warp_reduce_sum(v);
            if (lane == 0) g_kd_partials[blockIdx.x] = v;
        }
    } else {
        // ---- edge-loss path: cp.async smem ring + packed f32x2 stencil ----
        const int bid = blockIdx.x - KD_BLOCKS;
        const int bx = bid % GRID_X;
        const int by = bid / GRID_X;
        const int xbase = bx * (BX * TX);             // warp's 128-px segment
        const int y0 = (by * BY + wid) * TY;

        float* ring = &s_ring[wid * (DEPTH * 2 * ROWF)];
        const uint32_t ring_sa = (uint32_t)__cvta_generic_to_shared(ring);

        // --- stage one row (group) into slot: pred+tgt 16B per lane + halos ---
        auto issue_row = [&](int row, int slot) {
            float* sp = ring + slot * (2 * ROWF);
            float* st = sp + ROWF;
            uint32_t spa = ring_sa + slot * (2 * ROWF) * 4;
            uint32_t sta = spa + ROWF * 4;
            if ((unsigned)row < (unsigned)IMG_H) {
                const float* pp = pred + (size_t)row * IMG_W + xbase;
                const float* tp = tgt  + (size_t)row * IMG_W + xbase;
                cp16(spa + 16u * lane, pp + 4 * lane);
                cp16(sta + 16u * lane, tp + 4 * lane);
                if (lane == 0) {
                    if (xbase > 0) { cp4(spa + 128 * 4, pp - 1); cp4(sta + 128 * 4, tp - 1); }
                    else           { sp[128] = 0.0f; st[128] = 0.0f; }
                }
                if (lane == 1) {
                    if (xbase + 128 < IMG_W) { cp4(spa + 129 * 4, pp + 128); cp4(sta + 129 * 4, tp + 128); }
                    else                     { sp[129] = 0.0f; st[129] = 0.0f; }
                }
            } else {
                // out-of-image row: zero-fill
                float4 z = make_float4(0.f, 0.f, 0.f, 0.f);
                *(float4*)(sp + 4 * lane) = z;
                *(float4*)(st + 4 * lane) = z;
                if (lane == 0) { sp[128] = 0.f; st[128] = 0.f; }
                if (lane == 1) { sp[129] = 0.f; st[129] = 0.f; }
            }
            cp_commit();
        };

        // --- consume row from slot into packed ring row dst[6] ---
        auto consume_row = [&](int slot, u64 dst[6]) {
            const float* sp = ring + slot * (2 * ROWF);
            const float* st = sp + ROWF;
            float4 pv = *(const float4*)(sp + 4 * lane);
            float4 tv = *(const float4*)(st + 4 * lane);
            int li = (lane == 0)  ? 128 : 4 * lane - 1;
            int ri = (lane == 31) ? 129 : 4 * lane + 4;
            float pl = sp[li], pr = sp[ri];
            float tl = st[li], tr = st[ri];
            dst[0] = pack2(pl, tl);
            dst[1] = pack2(pv.x, tv.x); dst[2] = pack2(pv.y, tv.y);
            dst[3] = pack2(pv.z, tv.z); dst[4] = pack2(pv.w, tv.w);
            dst[5] = pack2(pr, tr);
        };

        // prologue: fill DEPTH rows (y0-1 .. y0+DEPTH-2), groups 0..DEPTH-1
#pragma unroll
        for (int g = 0; g < DEPTH; g++)
            issue_row(y0 - 1 + g, g);

        const u64 TWO2  = pack2(2.0f, 2.0f);
        const u64 NEG12 = pack2(-1.0f, -1.0f);

        u64 PT[3][6];
        cp_wait_3();          // groups 0,1 complete
        __syncwarp();
        consume_row(0, PT[0]);   // row y0-1
        consume_row(1, PT[1]);   // row y0

#pragma unroll
        for (int t = 0; t < TY; t++) {
            const int am = t % 3, bm = (t + 1) % 3, cm = (t + 2) % 3;
            // issue row y0+DEPTH-1+t into slot t%DEPTH
            {
                int r_i = y0 + DEPTH - 1 + t;
                if (r_i <= y0 + TY) issue_row(r_i, t % DEPTH);
                else cp_commit();                       // empty group keeps accounting
            }
            cp_wait_3();                                 // group t+2 complete
            __syncwarp();
            consume_row((t + 2) % DEPTH, PT[cm]);        // row y0+t+1

            const u64* ra = PT[am]; const u64* rb = PT[bm]; const u64* rc = PT[cm];
            u64 cs[6], dd[6];
#pragma unroll
            for (int i = 0; i < 6; i++) {
                cs[i] = add2(fma2(rb[i], TWO2, ra[i]), rc[i]);   // a + 2b + c
                dd[i] = fma2(ra[i], NEG12, rc[i]);               // c - a
            }
#pragma unroll
            for (int j = 0; j < 4; j++) {
                u64 ex = fma2(cs[j], NEG12, cs[j + 2]);
                u64 ey = add2(fma2(dd[j + 1], TWO2, dd[j]), dd[j + 2]);
                u64 s2 = fma2(ey, ey, mul2(ex, ex));
                float p2, t2;
                unpack2(s2, p2, t2);
                float df = fsqrt_approx(p2) - fsqrt_approx(t2);
                acc = fmaf(df, df, acc);
            }
        }

        float ws = warp_reduce_sum(acc);
        if (lane == 0) sred[wid] = ws;
        __syncthreads();
        if (wid == 0) {
            float v = (lane < 8) ? sred[lane] : 0.0f;
            v = warp_reduce_sum(v);
            if (lane == 0) g_edge_partials[bid] = v;
        }
    }

    // ---- grid-wide completion; last block reduces everything ----
    __threadfence();
    if (tid == 0) {
        unsigned int prev = atomicAdd(&g_done_count, 1u);
        s_last = (prev == TOTAL_BLOCKS - 1);
    }
    __syncthreads();
    if (!s_last) return;

    float e = 0.0f, kv = 0.0f;
    for (int i = tid; i < N_EDGE_BLOCKS; i += 256) e += g_edge_partials[i];
    if (tid < KD_BLOCKS) kv = g_kd_partials[tid];

    __shared__ float se[8], sk[8];
    float we = warp_reduce_sum(e);
    float wk = warp_reduce_sum(kv);
    if (lane == 0) { se[wid] = we; sk[wid] = wk; }
    __syncthreads();
    if (wid == 0) {
        float ve = (lane < 8) ? se[lane] : 0.0f;
        float vk = (lane < 8) ? sk[lane] : 0.0f;
        ve = warp_reduce_sum(ve);
        vk = warp_reduce_sum(vk);
        if (lane == 0) {
            float edge_loss = ve * (1.0f / ((float)IMG_W * (float)IMG_H));
            float constraint = vk / (float)K;
            out[0] = 1.0f * edge_loss + 0.5f * constraint;
            g_done_count = 0;
        }
    }
}

// ---------------------------------------------------------------------------
extern "C" void kernel_launch(void* const* d_in, const int* in_sizes, int n_in,
                              void* d_out, int out_size) {
    const float* kp   = (const float*)d_in[0];
    const float* pred = (const float*)d_in[2];
    const float* tgt  = (const float*)d_in[3];
    const int K = in_sizes[0] / 2;

    fused_kernel<<<TOTAL_BLOCKS, 256>>>(pred, tgt, kp, K, (float*)d_out);
}

// round 9
// speedup vs baseline: 1.7971x; 1.0652x over previous
#include <cuda_runtime.h>
#include <math.h>
#include <stdint.h>

#define IMG_W 4096
#define IMG_H 4096

#define BX 32
#define BY 8
#define TX 4
#define TY 16
#define GRID_X (IMG_W / (BX * TX))        // 32
#define GRID_Y (IMG_H / (BY * TY))        // 32
#define N_EDGE_BLOCKS (GRID_X * GRID_Y)   // 1024

#define KD_BLOCKS 64
#define TOTAL_BLOCKS (KD_BLOCKS + N_EDGE_BLOCKS)

#define DEPTH 4            // smem ring depth (rows in flight per warp)
#define ROWF 132           // floats per staged row: [0..127]=px, 128=L, 129=R, 2 pad

__device__ float g_edge_partials[N_EDGE_BLOCKS];
__device__ float g_kd_partials[KD_BLOCKS];
__device__ unsigned int g_done_count;

typedef unsigned long long u64;

// ---- packed f32x2 helpers ----
__device__ __forceinline__ u64 pack2(float lo, float hi) {
    u64 r; asm("mov.b64 %0, {%1, %2};" : "=l"(r) : "f"(lo), "f"(hi)); return r;
}
__device__ __forceinline__ void unpack2(u64 v, float& lo, float& hi) {
    asm("mov.b64 {%0, %1}, %2;" : "=f"(lo), "=f"(hi) : "l"(v));
}
__device__ __forceinline__ u64 add2(u64 a, u64 b) {
    u64 r; asm("add.rn.f32x2 %0, %1, %2;" : "=l"(r) : "l"(a), "l"(b)); return r;
}
__device__ __forceinline__ u64 mul2(u64 a, u64 b) {
    u64 r; asm("mul.rn.f32x2 %0, %1, %2;" : "=l"(r) : "l"(a), "l"(b)); return r;
}
__device__ __forceinline__ u64 fma2(u64 a, u64 b, u64 c) {
    u64 r; asm("fma.rn.f32x2 %0, %1, %2, %3;" : "=l"(r) : "l"(a), "l"(b), "l"(c)); return r;
}

__device__ __forceinline__ float fsqrt_approx(float x) {
    float r; asm("sqrt.approx.f32 %0, %1;" : "=f"(r) : "f"(x)); return r;
}

__device__ __forceinline__ float warp_reduce_sum(float v) {
#pragma unroll
    for (int off = 16; off > 0; off >>= 1)
        v += __shfl_down_sync(0xFFFFFFFFu, v, off);
    return v;
}

// ---- cp.async primitives ----
__device__ __forceinline__ void cp16(uint32_t dst, const float* src) {
    asm volatile("cp.async.cg.shared.global [%0], [%1], 16;" :: "r"(dst), "l"(src));
}
__device__ __forceinline__ void cp4(uint32_t dst, const float* src) {
    asm volatile("cp.async.ca.shared.global [%0], [%1], 4;" :: "r"(dst), "l"(src));
}
__device__ __forceinline__ void cp_commit() {
    asm volatile("cp.async.commit_group;" ::: "memory");
}
__device__ __forceinline__ void cp_wait_2() {
    asm volatile("cp.async.wait_group 2;" ::: "memory");   // DEPTH-2
}

// Sobel edge at (y,x) from zero-padded seg (kd path, scattered)
__device__ __forceinline__ float edge_at(const float* __restrict__ seg, int y, int x) {
    float v[3][3];
#pragma unroll
    for (int dy = 0; dy < 3; dy++)
#pragma unroll
        for (int dx = 0; dx < 3; dx++) {
            int yy = y - 1 + dy, xx = x - 1 + dx;
            v[dy][dx] = ((unsigned)yy < (unsigned)IMG_H && (unsigned)xx < (unsigned)IMG_W)
                        ? __ldg(seg + (size_t)yy * IMG_W + xx) : 0.0f;
        }
    float ex = (v[0][2] + 2.0f * v[1][2] + v[2][2]) - (v[0][0] + 2.0f * v[1][0] + v[2][0]);
    float ey = (v[2][0] + 2.0f * v[2][1] + v[2][2]) - (v[0][0] + 2.0f * v[0][1] + v[0][2]);
    return fsqrt_approx(ex * ex + ey * ey);
}

// ---------------------------------------------------------------------------
__global__ __launch_bounds__(256, 4)
void fused_kernel(const float* __restrict__ pred, const float* __restrict__ tgt,
                  const float* __restrict__ kp, int K, float* __restrict__ out) {
    const int tid = threadIdx.x;
    const int lane = tid & 31;
    const int wid  = tid >> 5;
    float acc = 0.0f;
    __shared__ float sred[8];
    __shared__ bool s_last;
    // per-warp staging rings: [warp][slot][img][ROWF]
    __shared__ __align__(16) float s_ring[8 * DEPTH * 2 * ROWF];

    if (blockIdx.x < KD_BLOCKS) {
        // ---- keypoint path: kd(k) = sum_{du,dv in -1..2} Wx*Wy*edge ----
        const int idx = blockIdx.x * 256 + tid;
        const int k    = idx >> 4;
        const int cell = idx & 15;
        if (k < K) {
            float gx = __ldg(kp + 2 * k);
            float gy = __ldg(kp + 2 * k + 1);
            float fx = (gx + 1.0f) * (IMG_W * 0.5f) - 0.5f;
            float fy = (gy + 1.0f) * (IMG_H * 0.5f) - 0.5f;
            float flx = floorf(fx), fly = floorf(fy);
            int x0 = (int)flx, y0 = (int)fly;
            float wx1 = fx - flx, wy1 = fy - fly;
            float wx0 = 1.0f - wx1, wy0 = 1.0f - wy1;
            float ax0 = ((unsigned)x0 < (unsigned)IMG_W) ? wx0 : 0.0f;
            float ax1 = ((unsigned)(x0 + 1) < (unsigned)IMG_W) ? wx1 : 0.0f;
            float ay0 = ((unsigned)y0 < (unsigned)IMG_H) ? wy0 : 0.0f;
            float ay1 = ((unsigned)(y0 + 1) < (unsigned)IMG_H) ? wy1 : 0.0f;

            int du = (cell & 3) - 1;
            int dv = (cell >> 2) - 1;
            float Wx = ((du <= 1) ? ax0 : 0.0f) + ((du >= 0) ? ax1 : 0.0f);
            float Wy = ((dv <= 1) ? ay0 : 0.0f) + ((dv >= 0) ? ay1 : 0.0f);
            float W = Wx * Wy;
            int cx = x0 + du, cy = y0 + dv;
            if (W != 0.0f && (unsigned)cx < (unsigned)IMG_W && (unsigned)cy < (unsigned)IMG_H)
                acc = W * edge_at(pred, cy, cx);
        }
        float ws = warp_reduce_sum(acc);
        if (lane == 0) sred[wid] = ws;
        __syncthreads();
        if (wid == 0) {
            float v = (lane < 8) ? sred[lane] : 0.0f;
            v = warp_reduce_sum(v);
            if (lane == 0) g_kd_partials[blockIdx.x] = v;
        }
    } else {
        // ---- edge-loss path: cp.async smem ring + packed f32x2 stencil ----
        const int bid = blockIdx.x - KD_BLOCKS;
        const int bx = bid % GRID_X;
        const int by = bid / GRID_X;
        const int xbase = bx * (BX * TX);             // warp's 128-px segment
        const int y0 = (by * BY + wid) * TY;

        float* ring = &s_ring[wid * (DEPTH * 2 * ROWF)];
        const uint32_t ring_sa = (uint32_t)__cvta_generic_to_shared(ring);

        // --- stage one row (group) into slot: pred+tgt 16B per lane + halos ---
        auto issue_row = [&](int row, int slot) {
            float* sp = ring + slot * (2 * ROWF);
            float* st = sp + ROWF;
            uint32_t spa = ring_sa + slot * (2 * ROWF) * 4;
            uint32_t sta = spa + ROWF * 4;
            if ((unsigned)row < (unsigned)IMG_H) {
                const float* pp = pred + (size_t)row * IMG_W + xbase;
                const float* tp = tgt  + (size_t)row * IMG_W + xbase;
                cp16(spa + 16u * lane, pp + 4 * lane);
                cp16(sta + 16u * lane, tp + 4 * lane);
                if (lane == 0) {
                    if (xbase > 0) { cp4(spa + 128 * 4, pp - 1); cp4(sta + 128 * 4, tp - 1); }
                    else           { sp[128] = 0.0f; st[128] = 0.0f; }
                }
                if (lane == 1) {
                    if (xbase + 128 < IMG_W) { cp4(spa + 129 * 4, pp + 128); cp4(sta + 129 * 4, tp + 128); }
                    else                     { sp[129] = 0.0f; st[129] = 0.0f; }
                }
            } else {
                float4 z = make_float4(0.f, 0.f, 0.f, 0.f);
                *(float4*)(sp + 4 * lane) = z;
                *(float4*)(st + 4 * lane) = z;
                if (lane == 0) { sp[128] = 0.f; st[128] = 0.f; }
                if (lane == 1) { sp[129] = 0.f; st[129] = 0.f; }
            }
            cp_commit();
        };

        // --- consume row from slot into packed ring row dst[6] ---
        auto consume_row = [&](int slot, u64 dst[6]) {
            const float* sp = ring + slot * (2 * ROWF);
            const float* st = sp + ROWF;
            float4 pv = *(const float4*)(sp + 4 * lane);
            float4 tv = *(const float4*)(st + 4 * lane);
            int li = (lane == 0)  ? 128 : 4 * lane - 1;
            int ri = (lane == 31) ? 129 : 4 * lane + 4;
            float pl = sp[li], pr = sp[ri];
            float tl = st[li], tr = st[ri];
            dst[0] = pack2(pl, tl);
            dst[1] = pack2(pv.x, tv.x); dst[2] = pack2(pv.y, tv.y);
            dst[3] = pack2(pv.z, tv.z); dst[4] = pack2(pv.w, tv.w);
            dst[5] = pack2(pr, tr);
        };

        // prologue: fill DEPTH rows (y0-1 .. y0+DEPTH-2), groups 0..DEPTH-1
#pragma unroll
        for (int g = 0; g < DEPTH; g++)
            issue_row(y0 - 1 + g, g);

        const u64 TWO2  = pack2(2.0f, 2.0f);
        const u64 NEG12 = pack2(-1.0f, -1.0f);

        u64 PT[3][6];
        cp_wait_2();          // groups 0,1 complete
        __syncwarp();
        consume_row(0, PT[0]);   // row y0-1
        consume_row(1, PT[1]);   // row y0

#pragma unroll
        for (int t = 0; t < TY; t++) {
            const int am = t % 3, bm = (t + 1) % 3, cm = (t + 2) % 3;
            // issue row y0+DEPTH-1+t into slot t%DEPTH
            {
                int r_i = y0 + DEPTH - 1 + t;
                if (r_i <= y0 + TY) issue_row(r_i, t % DEPTH);
                else cp_commit();                       // empty group keeps accounting
            }
            cp_wait_2();                                 // group t+2 complete
            __syncwarp();
            consume_row((t + 2) % DEPTH, PT[cm]);        // row y0+t+1

            const u64* ra = PT[am]; const u64* rb = PT[bm]; const u64* rc = PT[cm];
            u64 cs[6], dd[6];
#pragma unroll
            for (int i = 0; i < 6; i++) {
                cs[i] = add2(fma2(rb[i], TWO2, ra[i]), rc[i]);   // a + 2b + c
                dd[i] = fma2(ra[i], NEG12, rc[i]);               // c - a
            }
#pragma unroll
            for (int j = 0; j < 4; j++) {
                u64 ex = fma2(cs[j], NEG12, cs[j + 2]);
                u64 ey = add2(fma2(dd[j + 1], TWO2, dd[j]), dd[j + 2]);
                u64 s2 = fma2(ey, ey, mul2(ex, ex));
                float p2, t2;
                unpack2(s2, p2, t2);
                float df = fsqrt_approx(p2) - fsqrt_approx(t2);
                acc = fmaf(df, df, acc);
            }
        }

        float ws = warp_reduce_sum(acc);
        if (lane == 0) sred[wid] = ws;
        __syncthreads();
        if (wid == 0) {
            float v = (lane < 8) ? sred[lane] : 0.0f;
            v = warp_reduce_sum(v);
            if (lane == 0) g_edge_partials[bid] = v;
        }
    }

    // ---- grid-wide completion; last block reduces everything ----
    __threadfence();
    if (tid == 0) {
        unsigned int prev = atomicAdd(&g_done_count, 1u);
        s_last = (prev == TOTAL_BLOCKS - 1);
    }
    __syncthreads();
    if (!s_last) return;

    float e = 0.0f, kv = 0.0f;
    for (int i = tid; i < N_EDGE_BLOCKS; i += 256) e += g_edge_partials[i];
    if (tid < KD_BLOCKS) kv = g_kd_partials[tid];

    __shared__ float se[8], sk[8];
    float we = warp_reduce_sum(e);
    float wk = warp_reduce_sum(kv);
    if (lane == 0) { se[wid] = we; sk[wid] = wk; }
    __syncthreads();
    if (wid == 0) {
        float ve = (lane < 8) ? se[lane] : 0.0f;
        float vk = (lane < 8) ? sk[lane] : 0.0f;
        ve = warp_reduce_sum(ve);
        vk = warp_reduce_sum(vk);
        if (lane == 0) {
            float edge_loss = ve * (1.0f / ((float)IMG_W * (float)IMG_H));
            float constraint = vk / (float)K;
            out[0] = 1.0f * edge_loss + 0.5f * constraint;
            g_done_count = 0;
        }
    }
}

// ---------------------------------------------------------------------------
extern "C" void kernel_launch(void* const* d_in, const int* in_sizes, int n_in,
                              void* d_out, int out_size) {
    const float* kp   = (const float*)d_in[0];
    const float* pred = (const float*)d_in[2];
    const float* tgt  = (const float*)d_in[3];
    const int K = in_sizes[0] / 2;

    fused_kernel<<<TOTAL_BLOCKS, 256>>>(pred, tgt, kp, K, (float*)d_out);
}